// round 5
// baseline (speedup 1.0000x reference)
#include <cuda_runtime.h>
#include <cuda_fp16.h>
#include <math.h>

// ---------------------------------------------------------------------------
// out[e] = sigmoid( relu(x_e @ W1 + b1) @ W2 + b2 ),
// x_e = [h[src], rel_table[type], rel_table[q], time_table[time]]
//
// Decomposed into per-node / per-rel / per-time 128x128 projections (fp16),
// query projection + b1 folded into the rel rows. Edge pass = 3 uint4
// gathers + half2 relu-add-dot + sigmoid.
// ---------------------------------------------------------------------------

#define D 128
#define MAX_NODES 100000
#define MAX_RELS  500
#define MAX_TIMES 1000

__device__ __align__(128) __half g_node_proj[(size_t)MAX_NODES * D];
__device__ __align__(128) __half g_rel_proj[(size_t)MAX_RELS * D];   // + rq@W1c + b1
__device__ __align__(128) __half g_time_proj[(size_t)MAX_TIMES * D];
__device__ __align__(16)  __half g_w2h[D];

// ---- packed f32x2 helpers (sm_103a FFMA2) ---------------------------------
__device__ __forceinline__ unsigned long long pack2(float x, float y) {
    unsigned long long r;
    asm("mov.b64 %0, {%1, %2};"
        : "=l"(r) : "r"(__float_as_uint(x)), "r"(__float_as_uint(y)));
    return r;
}
__device__ __forceinline__ void unpack2(unsigned long long v, float& x, float& y) {
    unsigned a, b;
    asm("mov.b64 {%0, %1}, %2;" : "=r"(a), "=r"(b) : "l"(v));
    x = __uint_as_float(a); y = __uint_as_float(b);
}
__device__ __forceinline__ unsigned long long fma2(
    unsigned long long a, unsigned long long b, unsigned long long c) {
    unsigned long long d;
    asm("fma.rn.f32x2 %0, %1, %2, %3;" : "=l"(d) : "l"(a), "l"(b), "l"(c));
    return d;
}

#define BM 128
#define KC 32

// ---------------------------------------------------------------------------
// Fused prep kernel. Grid covers node / rel / time projection tiles.
// 256 threads, BM=BN=128 block tile, 8x8 register tile per thread, FFMA2.
// Block 0 additionally converts W2 -> fp16.
// ---------------------------------------------------------------------------
__global__ __launch_bounds__(256) void prep_kernel(
    const float* __restrict__ h,
    const float* __restrict__ rel_table,
    const float* __restrict__ time_table,
    const float* __restrict__ W1,
    const float* __restrict__ b1,
    const float* __restrict__ W2,
    const int* __restrict__ qptr,
    int n_nodes, int n_rels, int n_times)
{
    __shared__ float As[KC][BM];   // 16 KB, transposed A tile
    __shared__ float Bs[KC][D];    // 16 KB
    __shared__ float rq_s[D];

    const int nb_node = (n_nodes + BM - 1) / BM;
    const int nb_rel  = (n_rels  + BM - 1) / BM;

    const int tid = threadIdx.x;

    if (blockIdx.x == 0 && tid < D)
        g_w2h[tid] = __float2half(__ldg(W2 + tid));

    const float* A;
    __half* C;
    int w_off, M, m0;
    bool is_rel = false;

    int bx = blockIdx.x;
    if (bx < nb_node) {
        A = h; C = g_node_proj; w_off = 0; M = n_nodes; m0 = bx * BM;
    } else if (bx < nb_node + nb_rel) {
        A = rel_table; C = g_rel_proj; w_off = 128; M = n_rels;
        m0 = (bx - nb_node) * BM; is_rel = true;
    } else {
        A = time_table; C = g_time_proj; w_off = 384; M = n_times;
        m0 = (bx - nb_node - nb_rel) * BM;
    }

    const int tx = tid & 15;            // 8 cols each  -> 128 cols
    const int ty = tid >> 4;            // 8 rows each  -> 128 rows

    if (is_rel && tid < D) {
        int q = qptr[0];
        rq_s[tid] = __ldg(rel_table + (size_t)q * D + tid);
    }

    // acc2[rp][c]: rows (ty*8+2rp, ty*8+2rp+1), col tx*8+c
    unsigned long long acc2[4][8];
#pragma unroll
    for (int i = 0; i < 4; i++)
#pragma unroll
        for (int j = 0; j < 8; j++) acc2[i][j] = 0ull;

    for (int k0 = 0; k0 < D; k0 += KC) {
        __syncthreads();
        // A tile: 128 rows x 32 cols, stored transposed. 1024 float4 loads.
#pragma unroll
        for (int i = tid; i < BM * KC / 4; i += 256) {
            int row = i >> 3;           // /(KC/4)
            int c4  = i & 7;
            float4 v = make_float4(0.f, 0.f, 0.f, 0.f);
            int grow = m0 + row;
            if (grow < M)
                v = *(const float4*)(A + (size_t)grow * D + k0 + c4 * 4);
            As[c4 * 4 + 0][row] = v.x;
            As[c4 * 4 + 1][row] = v.y;
            As[c4 * 4 + 2][row] = v.z;
            As[c4 * 4 + 3][row] = v.w;
        }
        // B tile: 32 x 128 contiguous.
#pragma unroll
        for (int i = tid; i < KC * D / 4; i += 256) {
            int kk = i >> 5;
            int c4 = i & 31;
            *(float4*)(&Bs[kk][c4 * 4]) =
                *(const float4*)(W1 + (size_t)(w_off + k0 + kk) * D + c4 * 4);
        }
        __syncthreads();

#pragma unroll 8
        for (int kk = 0; kk < KC; kk++) {
            float4 a0 = *(const float4*)(&As[kk][ty * 8]);
            float4 a1 = *(const float4*)(&As[kk][ty * 8 + 4]);
            float4 b0 = *(const float4*)(&Bs[kk][tx * 8]);
            float4 b1v= *(const float4*)(&Bs[kk][tx * 8 + 4]);

            unsigned long long ap[4];
            ap[0] = pack2(a0.x, a0.y);
            ap[1] = pack2(a0.z, a0.w);
            ap[2] = pack2(a1.x, a1.y);
            ap[3] = pack2(a1.z, a1.w);

            unsigned long long bd[8];
            bd[0] = pack2(b0.x, b0.x);
            bd[1] = pack2(b0.y, b0.y);
            bd[2] = pack2(b0.z, b0.z);
            bd[3] = pack2(b0.w, b0.w);
            bd[4] = pack2(b1v.x, b1v.x);
            bd[5] = pack2(b1v.y, b1v.y);
            bd[6] = pack2(b1v.z, b1v.z);
            bd[7] = pack2(b1v.w, b1v.w);

#pragma unroll
            for (int rp = 0; rp < 4; rp++)
#pragma unroll
                for (int c = 0; c < 8; c++)
                    acc2[rp][c] = fma2(ap[rp], bd[c], acc2[rp][c]);
        }
    }

    // Column bias for rel blocks: rq @ W1[256:384] + b1 (8 cols per thread).
    float cb[8];
#pragma unroll
    for (int c = 0; c < 8; c++) cb[c] = 0.f;
    if (is_rel) {
        const float* Wc = W1 + (size_t)256 * D + tx * 8;
#pragma unroll 4
        for (int k = 0; k < D; k++) {
            float4 w0 = __ldg((const float4*)(Wc + (size_t)k * D));
            float4 w1 = __ldg((const float4*)(Wc + (size_t)k * D + 4));
            float rv  = rq_s[k];
            cb[0] += rv * w0.x; cb[1] += rv * w0.y;
            cb[2] += rv * w0.z; cb[3] += rv * w0.w;
            cb[4] += rv * w1.x; cb[5] += rv * w1.y;
            cb[6] += rv * w1.z; cb[7] += rv * w1.w;
        }
        float4 bb0 = __ldg((const float4*)(b1 + tx * 8));
        float4 bb1 = __ldg((const float4*)(b1 + tx * 8 + 4));
        cb[0] += bb0.x; cb[1] += bb0.y; cb[2] += bb0.z; cb[3] += bb0.w;
        cb[4] += bb1.x; cb[5] += bb1.y; cb[6] += bb1.z; cb[7] += bb1.w;
    }

#pragma unroll
    for (int rp = 0; rp < 4; rp++) {
        float r0[8], r1[8];
#pragma unroll
        for (int c = 0; c < 8; c++) {
            unpack2(acc2[rp][c], r0[c], r1[c]);
            r0[c] += cb[c]; r1[c] += cb[c];
        }
        int grow0 = m0 + ty * 8 + rp * 2;
#pragma unroll
        for (int rr = 0; rr < 2; rr++) {
            int grow = grow0 + rr;
            if (grow < M) {
                const float* rrow = rr ? r1 : r0;
                __half2 h0 = __floats2half2_rn(rrow[0], rrow[1]);
                __half2 h1 = __floats2half2_rn(rrow[2], rrow[3]);
                __half2 h2 = __floats2half2_rn(rrow[4], rrow[5]);
                __half2 h3 = __floats2half2_rn(rrow[6], rrow[7]);
                uint4 v;
                v.x = *(unsigned*)&h0; v.y = *(unsigned*)&h1;
                v.z = *(unsigned*)&h2; v.w = *(unsigned*)&h3;
                *(uint4*)(C + (size_t)grow * D + tx * 8) = v;
            }
        }
    }
}

// ---------------------------------------------------------------------------
// Edge pass: 16 lanes per edge, lane l handles features [8l, 8l+8).
// half2 arithmetic throughout; fp32 only for the final reduce + sigmoid.
// ---------------------------------------------------------------------------
__global__ __launch_bounds__(256) void edge_kernel(
    const int* __restrict__ edge_src,
    const int* __restrict__ edge_type,
    const int* __restrict__ edge_time,
    const float* __restrict__ b2,
    float* __restrict__ out, int E)
{
    unsigned gt = blockIdx.x * 256u + threadIdx.x;
    int e = (int)(gt >> 4);
    int l = threadIdx.x & 15;
    if (e >= E) return;

    int s = __ldg(edge_src + e);
    int r = __ldg(edge_type + e);
    int t = __ldg(edge_time + e);

    uint4 av = ((const uint4*)g_node_proj)[(size_t)s * 16 + l];
    uint4 bv = ((const uint4*)g_rel_proj )[(size_t)r * 16 + l];
    uint4 cv = ((const uint4*)g_time_proj)[(size_t)t * 16 + l];
    uint4 wv = ((const uint4*)g_w2h)[l];

    const __half2 z2 = __float2half2_rn(0.f);
    __half2 acc = z2;
    {
        __half2 x = __hmax2(__hadd2(__hadd2(*(__half2*)&av.x, *(__half2*)&bv.x),
                                    *(__half2*)&cv.x), z2);
        acc = __hfma2(x, *(__half2*)&wv.x, acc);
    }
    {
        __half2 x = __hmax2(__hadd2(__hadd2(*(__half2*)&av.y, *(__half2*)&bv.y),
                                    *(__half2*)&cv.y), z2);
        acc = __hfma2(x, *(__half2*)&wv.y, acc);
    }
    {
        __half2 x = __hmax2(__hadd2(__hadd2(*(__half2*)&av.z, *(__half2*)&bv.z),
                                    *(__half2*)&cv.z), z2);
        acc = __hfma2(x, *(__half2*)&wv.z, acc);
    }
    {
        __half2 x = __hmax2(__hadd2(__hadd2(*(__half2*)&av.w, *(__half2*)&bv.w),
                                    *(__half2*)&cv.w), z2);
        acc = __hfma2(x, *(__half2*)&wv.w, acc);
    }

    float2 f = __half22float2(acc);
    float dot = f.x + f.y;
#pragma unroll
    for (int off = 8; off; off >>= 1)
        dot += __shfl_xor_sync(0xffffffffu, dot, off);

    if (l == 0) {
        float alpha = dot + __ldg(b2);
        out[e] = 1.f / (1.f + __expf(-alpha));
    }
}

// ---------------------------------------------------------------------------
extern "C" void kernel_launch(void* const* d_in, const int* in_sizes, int n_in,
                              void* d_out, int out_size)
{
    const float* h          = (const float*)d_in[0];
    const int*   edge_index = (const int*)d_in[1];
    const int*   edge_type  = (const int*)d_in[2];
    const int*   edge_time  = (const int*)d_in[3];
    const int*   query_rel  = (const int*)d_in[4];
    const float* rel_table  = (const float*)d_in[5];
    const float* time_table = (const float*)d_in[6];
    const float* W1         = (const float*)d_in[7];
    const float* b1         = (const float*)d_in[8];
    const float* W2         = (const float*)d_in[9];
    const float* b2         = (const float*)d_in[10];
    float*       out        = (float*)d_out;

    const int n_nodes = in_sizes[0] / D;
    const int n_rels  = in_sizes[5] / D;
    const int n_times = in_sizes[6] / D;
    const int E       = in_sizes[2];

    const int nb_node = (n_nodes + BM - 1) / BM;
    const int nb_rel  = (n_rels  + BM - 1) / BM;
    const int nb_time = (n_times + BM - 1) / BM;

    prep_kernel<<<nb_node + nb_rel + nb_time, 256>>>(
        h, rel_table, time_table, W1, b1, W2, query_rel,
        n_nodes, n_rels, n_times);

    edge_kernel<<<(E + 15) / 16, 256>>>(
        edge_index, edge_type, edge_time, b2, out, E);
}

// round 6
// speedup vs baseline: 1.7803x; 1.7803x over previous
#include <cuda_runtime.h>
#include <cuda_fp16.h>
#include <math.h>

// ---------------------------------------------------------------------------
// out[e] = sigmoid( relu(x_e @ W1 + b1) @ W2 + b2 ),
// x_e = [h[src], rel_table[type], rel_table[q], time_table[time]]
//
// Decomposed into per-node / per-rel / per-time 128x128 projections (fp16),
// computed with HMMA (mma.sync m16n8k16) tensor cores. Query projection + b1
// folded into rel rows. Edge pass = 3 uint4 gathers + half2 math + sigmoid.
// ---------------------------------------------------------------------------

#define D 128
#define MAX_NODES 100000
#define MAX_RELS  500
#define MAX_TIMES 1000

__device__ __align__(128) __half g_node_proj[(size_t)MAX_NODES * D];
__device__ __align__(128) __half g_rel_proj[(size_t)MAX_RELS * D];   // + rq@W1c + b1
__device__ __align__(128) __half g_time_proj[(size_t)MAX_TIMES * D];
__device__ __align__(16)  __half g_w2h[D];

// ---- mma / ldmatrix helpers ------------------------------------------------
__device__ __forceinline__ unsigned smem_u32(const void* p) {
    return (unsigned)__cvta_generic_to_shared(p);
}
__device__ __forceinline__ void ldm_x4(unsigned* r, unsigned addr) {
    asm volatile("ldmatrix.sync.aligned.m8n8.x4.shared.b16 {%0,%1,%2,%3}, [%4];"
                 : "=r"(r[0]), "=r"(r[1]), "=r"(r[2]), "=r"(r[3]) : "r"(addr));
}
__device__ __forceinline__ void ldm_x4_trans(unsigned* r, unsigned addr) {
    asm volatile("ldmatrix.sync.aligned.m8n8.x4.trans.shared.b16 {%0,%1,%2,%3}, [%4];"
                 : "=r"(r[0]), "=r"(r[1]), "=r"(r[2]), "=r"(r[3]) : "r"(addr));
}
__device__ __forceinline__ void mma_16816(float* c, const unsigned* a,
                                          const unsigned* b) {
    asm volatile(
        "mma.sync.aligned.m16n8k16.row.col.f32.f16.f16.f32 "
        "{%0,%1,%2,%3}, {%4,%5,%6,%7}, {%8,%9}, {%0,%1,%2,%3};"
        : "+f"(c[0]), "+f"(c[1]), "+f"(c[2]), "+f"(c[3])
        : "r"(a[0]), "r"(a[1]), "r"(a[2]), "r"(a[3]), "r"(b[0]), "r"(b[1]));
}

#define BM 128
#define KC 64

// ---------------------------------------------------------------------------
// Fused prep kernel: 128x128 output tile per block, K=128 in two KC=64 steps.
// 8 warps; warp w owns rows (w&3)*32..+32, cols (w>>2)*64..+64
// (2 x 8 grid of m16n8k16 MMAs). Inputs converted fp32->fp16 on smem load.
// ---------------------------------------------------------------------------
__global__ __launch_bounds__(256) void prep_kernel(
    const float* __restrict__ h,
    const float* __restrict__ rel_table,
    const float* __restrict__ time_table,
    const float* __restrict__ W1,
    const float* __restrict__ b1,
    const float* __restrict__ W2,
    const int* __restrict__ qptr,
    int n_nodes, int n_rels, int n_times)
{
    __shared__ __align__(16) __half As[128][72];    // M x KC (+pad)
    __shared__ __align__(16) __half Bs[64][136];    // KC x N (+pad)
    __shared__ float cbias_s[D];
    __shared__ float rq_s[D];

    const int tid  = threadIdx.x;
    const int lane = tid & 31;
    const int w    = tid >> 5;
    const int warp_m = (w & 3) * 32;
    const int warp_n = (w >> 2) * 64;

    const int nb_node = (n_nodes + BM - 1) / BM;
    const int nb_rel  = (n_rels  + BM - 1) / BM;

    if (blockIdx.x == 0 && tid < D)
        g_w2h[tid] = __float2half(__ldg(W2 + tid));
    if (tid < D) cbias_s[tid] = 0.f;

    const float* A;
    __half* C;
    int w_off, M, m0;
    bool is_rel = false;

    int bx = blockIdx.x;
    if (bx < nb_node) {
        A = h; C = g_node_proj; w_off = 0; M = n_nodes; m0 = bx * BM;
    } else if (bx < nb_node + nb_rel) {
        A = rel_table; C = g_rel_proj; w_off = 128; M = n_rels;
        m0 = (bx - nb_node) * BM; is_rel = true;
    } else {
        A = time_table; C = g_time_proj; w_off = 384; M = n_times;
        m0 = (bx - nb_node - nb_rel) * BM;
    }

    if (is_rel && tid < D) {
        int q = qptr[0];
        rq_s[tid] = __ldg(rel_table + (size_t)q * D + tid);
    }

    float acc[2][8][4];
#pragma unroll
    for (int mi = 0; mi < 2; mi++)
#pragma unroll
        for (int ni = 0; ni < 8; ni++)
#pragma unroll
            for (int c = 0; c < 4; c++) acc[mi][ni][c] = 0.f;

    for (int k0 = 0; k0 < D; k0 += KC) {
        __syncthreads();
        // A tile: 128 x 64, fp32 -> fp16. 2048 float4 sources, 8 per thread.
#pragma unroll
        for (int it = 0; it < 8; it++) {
            int i   = tid + it * 256;
            int row = i >> 4;           // 16 float4 per row
            int c4  = i & 15;
            float4 v = make_float4(0.f, 0.f, 0.f, 0.f);
            int grow = m0 + row;
            if (grow < M)
                v = *(const float4*)(A + (size_t)grow * D + k0 + c4 * 4);
            __half2 h01 = __floats2half2_rn(v.x, v.y);
            __half2 h23 = __floats2half2_rn(v.z, v.w);
            uint2 pv;
            pv.x = *(unsigned*)&h01; pv.y = *(unsigned*)&h23;
            *(uint2*)(&As[row][c4 * 4]) = pv;
        }
        // B tile: 64 x 128, fp32 -> fp16. 2048 float4 sources.
#pragma unroll
        for (int it = 0; it < 8; it++) {
            int i   = tid + it * 256;
            int kk  = i >> 5;           // 32 float4 per row
            int c4  = i & 31;
            float4 v = *(const float4*)(W1 + (size_t)(w_off + k0 + kk) * D + c4 * 4);
            __half2 h01 = __floats2half2_rn(v.x, v.y);
            __half2 h23 = __floats2half2_rn(v.z, v.w);
            uint2 pv;
            pv.x = *(unsigned*)&h01; pv.y = *(unsigned*)&h23;
            *(uint2*)(&Bs[kk][c4 * 4]) = pv;
        }
        __syncthreads();

#pragma unroll
        for (int ks = 0; ks < KC / 16; ks++) {
            // A fragments: quads (m0-7,k0), (m8-15,k0), (m0-7,k8), (m8-15,k8)
            unsigned a[2][4];
            {
                int arow = (lane & 7) + ((lane >> 3) & 1) * 8;
                int acol = ks * 16 + (lane >> 4) * 8;
#pragma unroll
                for (int mi = 0; mi < 2; mi++)
                    ldm_x4(a[mi], smem_u32(&As[warp_m + mi * 16 + arow][acol]));
            }
            // B fragments: trans quads (k0-7,n0), (k8-15,n0), (k0-7,n8), (k8-15,n8)
            unsigned b[8][2];
            {
                int krow = ks * 16 + (lane & 7) + ((lane >> 3) & 1) * 8;
#pragma unroll
                for (int p = 0; p < 4; p++) {
                    unsigned r[4];
                    int ncol = warp_n + p * 16 + (lane >> 4) * 8;
                    ldm_x4_trans(r, smem_u32(&Bs[krow][ncol]));
                    b[2 * p][0]     = r[0]; b[2 * p][1]     = r[1];
                    b[2 * p + 1][0] = r[2]; b[2 * p + 1][1] = r[3];
                }
            }
#pragma unroll
            for (int mi = 0; mi < 2; mi++)
#pragma unroll
                for (int ni = 0; ni < 8; ni++)
                    mma_16816(acc[mi][ni], a[mi], b[ni]);
        }
    }

    // Rel blocks: fold rq @ W1[256:384] + b1 into a per-column bias.
    if (is_rel) {
        if (tid < D) {
            int j = tid;
            float s = __ldg(b1 + j);
            const float* Wc = W1 + (size_t)256 * D + j;
#pragma unroll 8
            for (int k = 0; k < D; k++)
                s += rq_s[k] * __ldg(Wc + (size_t)k * D);
            cbias_s[j] = s;
        }
        __syncthreads();
    }

    // Epilogue: c0,c1 -> (row, col..col+1); c2,c3 -> (row+8, ...)
    const int erow = lane >> 2;
    const int ecol = (lane & 3) * 2;
#pragma unroll
    for (int mi = 0; mi < 2; mi++) {
#pragma unroll
        for (int ni = 0; ni < 8; ni++) {
            int col = warp_n + ni * 8 + ecol;
            float cb0 = cbias_s[col], cb1 = cbias_s[col + 1];
            int r0 = m0 + warp_m + mi * 16 + erow;
            if (r0 < M) {
                __half2 v = __floats2half2_rn(acc[mi][ni][0] + cb0,
                                              acc[mi][ni][1] + cb1);
                *(__half2*)(C + (size_t)r0 * D + col) = v;
            }
            int r1 = r0 + 8;
            if (r1 < M) {
                __half2 v = __floats2half2_rn(acc[mi][ni][2] + cb0,
                                              acc[mi][ni][3] + cb1);
                *(__half2*)(C + (size_t)r1 * D + col) = v;
            }
        }
    }
}

// ---------------------------------------------------------------------------
// Edge pass: 16 lanes per edge, lane l handles features [8l, 8l+8).
// half2 arithmetic; fp32 only for the final reduce + sigmoid.
// ---------------------------------------------------------------------------
__global__ __launch_bounds__(256) void edge_kernel(
    const int* __restrict__ edge_src,
    const int* __restrict__ edge_type,
    const int* __restrict__ edge_time,
    const float* __restrict__ b2,
    float* __restrict__ out, int E)
{
    unsigned gt = blockIdx.x * 256u + threadIdx.x;
    int e = (int)(gt >> 4);
    int l = threadIdx.x & 15;
    if (e >= E) return;

    int s = __ldg(edge_src + e);
    int r = __ldg(edge_type + e);
    int t = __ldg(edge_time + e);

    uint4 av = ((const uint4*)g_node_proj)[(size_t)s * 16 + l];
    uint4 bv = ((const uint4*)g_rel_proj )[(size_t)r * 16 + l];
    uint4 cv = ((const uint4*)g_time_proj)[(size_t)t * 16 + l];
    uint4 wv = ((const uint4*)g_w2h)[l];

    const __half2 z2 = __float2half2_rn(0.f);
    __half2 acc = z2;
    {
        __half2 x = __hmax2(__hadd2(__hadd2(*(__half2*)&av.x, *(__half2*)&bv.x),
                                    *(__half2*)&cv.x), z2);
        acc = __hfma2(x, *(__half2*)&wv.x, acc);
    }
    {
        __half2 x = __hmax2(__hadd2(__hadd2(*(__half2*)&av.y, *(__half2*)&bv.y),
                                    *(__half2*)&cv.y), z2);
        acc = __hfma2(x, *(__half2*)&wv.y, acc);
    }
    {
        __half2 x = __hmax2(__hadd2(__hadd2(*(__half2*)&av.z, *(__half2*)&bv.z),
                                    *(__half2*)&cv.z), z2);
        acc = __hfma2(x, *(__half2*)&wv.z, acc);
    }
    {
        __half2 x = __hmax2(__hadd2(__hadd2(*(__half2*)&av.w, *(__half2*)&bv.w),
                                    *(__half2*)&cv.w), z2);
        acc = __hfma2(x, *(__half2*)&wv.w, acc);
    }

    float2 f = __half22float2(acc);
    float dot = f.x + f.y;
#pragma unroll
    for (int off = 8; off; off >>= 1)
        dot += __shfl_xor_sync(0xffffffffu, dot, off);

    if (l == 0) {
        float alpha = dot + __ldg(b2);
        out[e] = 1.f / (1.f + __expf(-alpha));
    }
}

// ---------------------------------------------------------------------------
extern "C" void kernel_launch(void* const* d_in, const int* in_sizes, int n_in,
                              void* d_out, int out_size)
{
    const float* h          = (const float*)d_in[0];
    const int*   edge_index = (const int*)d_in[1];
    const int*   edge_type  = (const int*)d_in[2];
    const int*   edge_time  = (const int*)d_in[3];
    const int*   query_rel  = (const int*)d_in[4];
    const float* rel_table  = (const float*)d_in[5];
    const float* time_table = (const float*)d_in[6];
    const float* W1         = (const float*)d_in[7];
    const float* b1         = (const float*)d_in[8];
    const float* W2         = (const float*)d_in[9];
    const float* b2         = (const float*)d_in[10];
    float*       out        = (float*)d_out;

    const int n_nodes = in_sizes[0] / D;
    const int n_rels  = in_sizes[5] / D;
    const int n_times = in_sizes[6] / D;
    const int E       = in_sizes[2];

    const int nb_node = (n_nodes + BM - 1) / BM;
    const int nb_rel  = (n_rels  + BM - 1) / BM;
    const int nb_time = (n_times + BM - 1) / BM;

    prep_kernel<<<nb_node + nb_rel + nb_time, 256>>>(
        h, rel_table, time_table, W1, b1, W2, query_rel,
        n_nodes, n_rels, n_times);

    edge_kernel<<<(E + 15) / 16, 256>>>(
        edge_index, edge_type, edge_time, b2, out, E);
}

// round 7
// speedup vs baseline: 2.2613x; 1.2702x over previous
#include <cuda_runtime.h>
#include <cuda_fp16.h>
#include <math.h>

// ---------------------------------------------------------------------------
// out[e] = sigmoid( relu(x_e @ W1 + b1) @ W2 + b2 ),
// x_e = [h[src], rel_table[type], rel_table[q], time_table[time]]
//
// Decomposed into per-node / per-rel / per-time 128x128 projections (fp16),
// computed with HMMA tensor cores. Query projection + b1 folded into rel
// rows. Edge pass = 3 uint4 gathers + half2 math + sigmoid, 2 edges in
// flight per 16-lane group (MLP), W2 hoisted to registers.
// ---------------------------------------------------------------------------

#define D 128
#define MAX_NODES 100000
#define MAX_RELS  500
#define MAX_TIMES 1000

__device__ __align__(128) __half g_node_proj[(size_t)MAX_NODES * D];
__device__ __align__(128) __half g_rel_proj[(size_t)MAX_RELS * D];   // + rq@W1c + b1
__device__ __align__(128) __half g_time_proj[(size_t)MAX_TIMES * D];
__device__ __align__(16)  __half g_w2h[D];

// ---- mma / ldmatrix helpers ------------------------------------------------
__device__ __forceinline__ unsigned smem_u32(const void* p) {
    return (unsigned)__cvta_generic_to_shared(p);
}
__device__ __forceinline__ void ldm_x4(unsigned* r, unsigned addr) {
    asm volatile("ldmatrix.sync.aligned.m8n8.x4.shared.b16 {%0,%1,%2,%3}, [%4];"
                 : "=r"(r[0]), "=r"(r[1]), "=r"(r[2]), "=r"(r[3]) : "r"(addr));
}
__device__ __forceinline__ void ldm_x4_trans(unsigned* r, unsigned addr) {
    asm volatile("ldmatrix.sync.aligned.m8n8.x4.trans.shared.b16 {%0,%1,%2,%3}, [%4];"
                 : "=r"(r[0]), "=r"(r[1]), "=r"(r[2]), "=r"(r[3]) : "r"(addr));
}
__device__ __forceinline__ void mma_16816(float* c, const unsigned* a,
                                          const unsigned* b) {
    asm volatile(
        "mma.sync.aligned.m16n8k16.row.col.f32.f16.f16.f32 "
        "{%0,%1,%2,%3}, {%4,%5,%6,%7}, {%8,%9}, {%0,%1,%2,%3};"
        : "+f"(c[0]), "+f"(c[1]), "+f"(c[2]), "+f"(c[3])
        : "r"(a[0]), "r"(a[1]), "r"(a[2]), "r"(a[3]), "r"(b[0]), "r"(b[1]));
}

#define BM 128
#define KC 64

// ---------------------------------------------------------------------------
// Fused prep kernel: 128x128 output tile per block, K=128 in two KC=64 steps.
// 8 warps; warp w owns rows (w&3)*32..+32, cols (w>>2)*64..+64.
// ---------------------------------------------------------------------------
__global__ __launch_bounds__(256) void prep_kernel(
    const float* __restrict__ h,
    const float* __restrict__ rel_table,
    const float* __restrict__ time_table,
    const float* __restrict__ W1,
    const float* __restrict__ b1,
    const float* __restrict__ W2,
    const int* __restrict__ qptr,
    int n_nodes, int n_rels, int n_times)
{
    __shared__ __align__(16) __half As[128][72];    // M x KC (+pad)
    __shared__ __align__(16) __half Bs[64][136];    // KC x N (+pad)
    __shared__ float cbias_s[D];
    __shared__ float rq_s[D];

    const int tid  = threadIdx.x;
    const int lane = tid & 31;
    const int w    = tid >> 5;
    const int warp_m = (w & 3) * 32;
    const int warp_n = (w >> 2) * 64;

    const int nb_node = (n_nodes + BM - 1) / BM;
    const int nb_rel  = (n_rels  + BM - 1) / BM;

    if (blockIdx.x == 0 && tid < D)
        g_w2h[tid] = __float2half(__ldg(W2 + tid));
    if (tid < D) cbias_s[tid] = 0.f;

    const float* A;
    __half* C;
    int w_off, M, m0;
    bool is_rel = false;

    int bx = blockIdx.x;
    if (bx < nb_node) {
        A = h; C = g_node_proj; w_off = 0; M = n_nodes; m0 = bx * BM;
    } else if (bx < nb_node + nb_rel) {
        A = rel_table; C = g_rel_proj; w_off = 128; M = n_rels;
        m0 = (bx - nb_node) * BM; is_rel = true;
    } else {
        A = time_table; C = g_time_proj; w_off = 384; M = n_times;
        m0 = (bx - nb_node - nb_rel) * BM;
    }

    if (is_rel && tid < D) {
        int q = qptr[0];
        rq_s[tid] = __ldg(rel_table + (size_t)q * D + tid);
    }

    float acc[2][8][4];
#pragma unroll
    for (int mi = 0; mi < 2; mi++)
#pragma unroll
        for (int ni = 0; ni < 8; ni++)
#pragma unroll
            for (int c = 0; c < 4; c++) acc[mi][ni][c] = 0.f;

    for (int k0 = 0; k0 < D; k0 += KC) {
        __syncthreads();
        // A tile: 128 x 64, fp32 -> fp16.
#pragma unroll
        for (int it = 0; it < 8; it++) {
            int i   = tid + it * 256;
            int row = i >> 4;
            int c4  = i & 15;
            float4 v = make_float4(0.f, 0.f, 0.f, 0.f);
            int grow = m0 + row;
            if (grow < M)
                v = *(const float4*)(A + (size_t)grow * D + k0 + c4 * 4);
            __half2 h01 = __floats2half2_rn(v.x, v.y);
            __half2 h23 = __floats2half2_rn(v.z, v.w);
            uint2 pv;
            pv.x = *(unsigned*)&h01; pv.y = *(unsigned*)&h23;
            *(uint2*)(&As[row][c4 * 4]) = pv;
        }
        // B tile: 64 x 128, fp32 -> fp16.
#pragma unroll
        for (int it = 0; it < 8; it++) {
            int i   = tid + it * 256;
            int kk  = i >> 5;
            int c4  = i & 31;
            float4 v = *(const float4*)(W1 + (size_t)(w_off + k0 + kk) * D + c4 * 4);
            __half2 h01 = __floats2half2_rn(v.x, v.y);
            __half2 h23 = __floats2half2_rn(v.z, v.w);
            uint2 pv;
            pv.x = *(unsigned*)&h01; pv.y = *(unsigned*)&h23;
            *(uint2*)(&Bs[kk][c4 * 4]) = pv;
        }
        __syncthreads();

#pragma unroll
        for (int ks = 0; ks < KC / 16; ks++) {
            unsigned a[2][4];
            {
                int arow = (lane & 7) + ((lane >> 3) & 1) * 8;
                int acol = ks * 16 + (lane >> 4) * 8;
#pragma unroll
                for (int mi = 0; mi < 2; mi++)
                    ldm_x4(a[mi], smem_u32(&As[warp_m + mi * 16 + arow][acol]));
            }
            unsigned b[8][2];
            {
                int krow = ks * 16 + (lane & 7) + ((lane >> 3) & 1) * 8;
#pragma unroll
                for (int p = 0; p < 4; p++) {
                    unsigned r[4];
                    int ncol = warp_n + p * 16 + (lane >> 4) * 8;
                    ldm_x4_trans(r, smem_u32(&Bs[krow][ncol]));
                    b[2 * p][0]     = r[0]; b[2 * p][1]     = r[1];
                    b[2 * p + 1][0] = r[2]; b[2 * p + 1][1] = r[3];
                }
            }
#pragma unroll
            for (int mi = 0; mi < 2; mi++)
#pragma unroll
                for (int ni = 0; ni < 8; ni++)
                    mma_16816(acc[mi][ni], a[mi], b[ni]);
        }
    }

    if (is_rel) {
        if (tid < D) {
            int j = tid;
            float s = __ldg(b1 + j);
            const float* Wc = W1 + (size_t)256 * D + j;
#pragma unroll 8
            for (int k = 0; k < D; k++)
                s += rq_s[k] * __ldg(Wc + (size_t)k * D);
            cbias_s[j] = s;
        }
        __syncthreads();
    }

    const int erow = lane >> 2;
    const int ecol = (lane & 3) * 2;
#pragma unroll
    for (int mi = 0; mi < 2; mi++) {
#pragma unroll
        for (int ni = 0; ni < 8; ni++) {
            int col = warp_n + ni * 8 + ecol;
            float cb0 = cbias_s[col], cb1 = cbias_s[col + 1];
            int r0 = m0 + warp_m + mi * 16 + erow;
            if (r0 < M) {
                __half2 v = __floats2half2_rn(acc[mi][ni][0] + cb0,
                                              acc[mi][ni][1] + cb1);
                *(__half2*)(C + (size_t)r0 * D + col) = v;
            }
            int r1 = r0 + 8;
            if (r1 < M) {
                __half2 v = __floats2half2_rn(acc[mi][ni][2] + cb0,
                                              acc[mi][ni][3] + cb1);
                *(__half2*)(C + (size_t)r1 * D + col) = v;
            }
        }
    }
}

// ---------------------------------------------------------------------------
// Edge pass: grid-stride, 16 lanes per edge, 2 edges per group-iteration so
// 6 table LDG.128s are in flight before any math. W2 hoisted to registers.
// ---------------------------------------------------------------------------
__device__ __forceinline__ float edge_partial(uint4 av, uint4 bv, uint4 cv,
                                              uint4 wv)
{
    const __half2 z2 = __float2half2_rn(0.f);
    __half2 acc;
    {
        __half2 x = __hmax2(__hadd2(__hadd2(*(__half2*)&av.x, *(__half2*)&bv.x),
                                    *(__half2*)&cv.x), z2);
        acc = __hmul2(x, *(__half2*)&wv.x);
    }
    {
        __half2 x = __hmax2(__hadd2(__hadd2(*(__half2*)&av.y, *(__half2*)&bv.y),
                                    *(__half2*)&cv.y), z2);
        acc = __hfma2(x, *(__half2*)&wv.y, acc);
    }
    {
        __half2 x = __hmax2(__hadd2(__hadd2(*(__half2*)&av.z, *(__half2*)&bv.z),
                                    *(__half2*)&cv.z), z2);
        acc = __hfma2(x, *(__half2*)&wv.z, acc);
    }
    {
        __half2 x = __hmax2(__hadd2(__hadd2(*(__half2*)&av.w, *(__half2*)&bv.w),
                                    *(__half2*)&cv.w), z2);
        acc = __hfma2(x, *(__half2*)&wv.w, acc);
    }
    float2 f = __half22float2(acc);
    return f.x + f.y;
}

__global__ __launch_bounds__(256) void edge_kernel(
    const int* __restrict__ edge_src,
    const int* __restrict__ edge_type,
    const int* __restrict__ edge_time,
    const float* __restrict__ b2,
    float* __restrict__ out, int E)
{
    const int l = threadIdx.x & 15;                         // lane within group
    // global 16-lane group id
    const int group  = (int)((blockIdx.x * 256u + threadIdx.x) >> 4);
    const int ngroup = (int)(gridDim.x * 256u / 16u);

    const uint4 wv  = ((const uint4*)g_w2h)[l];             // hoisted
    const float b2v = __ldg(b2);

    // Each group handles edges (2*group, 2*group+1), stride 2*ngroup.
    for (int e0 = group * 2; e0 < E; e0 += ngroup * 2) {
        int e1 = e0 + 1;
        bool has1 = (e1 < E);

        int sA = __ldg(edge_src  + e0);
        int rA = __ldg(edge_type + e0);
        int tA = __ldg(edge_time + e0);
        int sB = has1 ? __ldg(edge_src  + e1) : sA;
        int rB = has1 ? __ldg(edge_type + e1) : rA;
        int tB = has1 ? __ldg(edge_time + e1) : tA;

        uint4 avA = ((const uint4*)g_node_proj)[(size_t)sA * 16 + l];
        uint4 bvA = ((const uint4*)g_rel_proj )[(size_t)rA * 16 + l];
        uint4 cvA = ((const uint4*)g_time_proj)[(size_t)tA * 16 + l];
        uint4 avB = ((const uint4*)g_node_proj)[(size_t)sB * 16 + l];
        uint4 bvB = ((const uint4*)g_rel_proj )[(size_t)rB * 16 + l];
        uint4 cvB = ((const uint4*)g_time_proj)[(size_t)tB * 16 + l];

        float dA = edge_partial(avA, bvA, cvA, wv);
        float dB = edge_partial(avB, bvB, cvB, wv);

#pragma unroll
        for (int off = 8; off; off >>= 1) {
            dA += __shfl_xor_sync(0xffffffffu, dA, off);
            dB += __shfl_xor_sync(0xffffffffu, dB, off);
        }

        if (l == 0) {
            out[e0] = 1.f / (1.f + __expf(-(dA + b2v)));
            if (has1)
                out[e1] = 1.f / (1.f + __expf(-(dB + b2v)));
        }
    }
}

// ---------------------------------------------------------------------------
extern "C" void kernel_launch(void* const* d_in, const int* in_sizes, int n_in,
                              void* d_out, int out_size)
{
    const float* h          = (const float*)d_in[0];
    const int*   edge_index = (const int*)d_in[1];
    const int*   edge_type  = (const int*)d_in[2];
    const int*   edge_time  = (const int*)d_in[3];
    const int*   query_rel  = (const int*)d_in[4];
    const float* rel_table  = (const float*)d_in[5];
    const float* time_table = (const float*)d_in[6];
    const float* W1         = (const float*)d_in[7];
    const float* b1         = (const float*)d_in[8];
    const float* W2         = (const float*)d_in[9];
    const float* b2         = (const float*)d_in[10];
    float*       out        = (float*)d_out;

    const int n_nodes = in_sizes[0] / D;
    const int n_rels  = in_sizes[5] / D;
    const int n_times = in_sizes[6] / D;
    const int E       = in_sizes[2];

    const int nb_node = (n_nodes + BM - 1) / BM;
    const int nb_rel  = (n_rels  + BM - 1) / BM;
    const int nb_time = (n_times + BM - 1) / BM;

    prep_kernel<<<nb_node + nb_rel + nb_time, 256>>>(
        h, rel_table, time_table, W1, b1, W2, query_rel,
        n_nodes, n_rels, n_times);

    // Persistent-ish edge grid: 2048 blocks x 8 warps x 2 groups x 2 edges
    // per iteration -> ~15 iterations per group over 1M edges.
    edge_kernel<<<2048, 256>>>(edge_index, edge_type, edge_time, b2, out, E);
}

// round 8
// speedup vs baseline: 2.2906x; 1.0130x over previous
#include <cuda_runtime.h>
#include <cuda_fp16.h>
#include <math.h>

// ---------------------------------------------------------------------------
// out[e] = sigmoid( relu(x_e @ W1 + b1) @ W2 + b2 ),
// x_e = [h[src], rel_table[type], rel_table[q], time_table[time]]
//
// Decomposed into per-node / per-rel / per-time 128x128 projections (fp16),
// computed with HMMA tensor cores. Query projection + b1 folded into rel
// rows. Edge pass: 8 lanes/edge, 2 edges (one int2 pair) per group-iter,
// 12 independent LDG.128 in flight, 3-level shuffle reduce.
// ---------------------------------------------------------------------------

#define D 128
#define MAX_NODES 100000
#define MAX_RELS  500
#define MAX_TIMES 1000

__device__ __align__(128) __half g_node_proj[(size_t)MAX_NODES * D];
__device__ __align__(128) __half g_rel_proj[(size_t)MAX_RELS * D];   // + rq@W1c + b1
__device__ __align__(128) __half g_time_proj[(size_t)MAX_TIMES * D];
__device__ __align__(16)  __half g_w2h[D];

// ---- mma / ldmatrix helpers ------------------------------------------------
__device__ __forceinline__ unsigned smem_u32(const void* p) {
    return (unsigned)__cvta_generic_to_shared(p);
}
__device__ __forceinline__ void ldm_x4(unsigned* r, unsigned addr) {
    asm volatile("ldmatrix.sync.aligned.m8n8.x4.shared.b16 {%0,%1,%2,%3}, [%4];"
                 : "=r"(r[0]), "=r"(r[1]), "=r"(r[2]), "=r"(r[3]) : "r"(addr));
}
__device__ __forceinline__ void ldm_x4_trans(unsigned* r, unsigned addr) {
    asm volatile("ldmatrix.sync.aligned.m8n8.x4.trans.shared.b16 {%0,%1,%2,%3}, [%4];"
                 : "=r"(r[0]), "=r"(r[1]), "=r"(r[2]), "=r"(r[3]) : "r"(addr));
}
__device__ __forceinline__ void mma_16816(float* c, const unsigned* a,
                                          const unsigned* b) {
    asm volatile(
        "mma.sync.aligned.m16n8k16.row.col.f32.f16.f16.f32 "
        "{%0,%1,%2,%3}, {%4,%5,%6,%7}, {%8,%9}, {%0,%1,%2,%3};"
        : "+f"(c[0]), "+f"(c[1]), "+f"(c[2]), "+f"(c[3])
        : "r"(a[0]), "r"(a[1]), "r"(a[2]), "r"(a[3]), "r"(b[0]), "r"(b[1]));
}

#define BM 128
#define KC 64

// ---------------------------------------------------------------------------
// Fused prep kernel: 128x128 output tile per block, K=128 in two KC=64 steps.
// 8 warps; warp w owns rows (w&3)*32..+32, cols (w>>2)*64..+64.
// ---------------------------------------------------------------------------
__global__ __launch_bounds__(256) void prep_kernel(
    const float* __restrict__ h,
    const float* __restrict__ rel_table,
    const float* __restrict__ time_table,
    const float* __restrict__ W1,
    const float* __restrict__ b1,
    const float* __restrict__ W2,
    const int* __restrict__ qptr,
    int n_nodes, int n_rels, int n_times)
{
    __shared__ __align__(16) __half As[128][72];    // M x KC (+pad)
    __shared__ __align__(16) __half Bs[64][136];    // KC x N (+pad)
    __shared__ float cbias_s[D];
    __shared__ float rq_s[D];

    const int tid  = threadIdx.x;
    const int lane = tid & 31;
    const int w    = tid >> 5;
    const int warp_m = (w & 3) * 32;
    const int warp_n = (w >> 2) * 64;

    const int nb_node = (n_nodes + BM - 1) / BM;
    const int nb_rel  = (n_rels  + BM - 1) / BM;

    if (blockIdx.x == 0 && tid < D)
        g_w2h[tid] = __float2half(__ldg(W2 + tid));
    if (tid < D) cbias_s[tid] = 0.f;

    const float* A;
    __half* C;
    int w_off, M, m0;
    bool is_rel = false;

    int bx = blockIdx.x;
    if (bx < nb_node) {
        A = h; C = g_node_proj; w_off = 0; M = n_nodes; m0 = bx * BM;
    } else if (bx < nb_node + nb_rel) {
        A = rel_table; C = g_rel_proj; w_off = 128; M = n_rels;
        m0 = (bx - nb_node) * BM; is_rel = true;
    } else {
        A = time_table; C = g_time_proj; w_off = 384; M = n_times;
        m0 = (bx - nb_node - nb_rel) * BM;
    }

    if (is_rel && tid < D) {
        int q = qptr[0];
        rq_s[tid] = __ldg(rel_table + (size_t)q * D + tid);
    }

    float acc[2][8][4];
#pragma unroll
    for (int mi = 0; mi < 2; mi++)
#pragma unroll
        for (int ni = 0; ni < 8; ni++)
#pragma unroll
            for (int c = 0; c < 4; c++) acc[mi][ni][c] = 0.f;

    for (int k0 = 0; k0 < D; k0 += KC) {
        __syncthreads();
        // A tile: 128 x 64, fp32 -> fp16.
#pragma unroll
        for (int it = 0; it < 8; it++) {
            int i   = tid + it * 256;
            int row = i >> 4;
            int c4  = i & 15;
            float4 v = make_float4(0.f, 0.f, 0.f, 0.f);
            int grow = m0 + row;
            if (grow < M)
                v = *(const float4*)(A + (size_t)grow * D + k0 + c4 * 4);
            __half2 h01 = __floats2half2_rn(v.x, v.y);
            __half2 h23 = __floats2half2_rn(v.z, v.w);
            uint2 pv;
            pv.x = *(unsigned*)&h01; pv.y = *(unsigned*)&h23;
            *(uint2*)(&As[row][c4 * 4]) = pv;
        }
        // B tile: 64 x 128, fp32 -> fp16.
#pragma unroll
        for (int it = 0; it < 8; it++) {
            int i   = tid + it * 256;
            int kk  = i >> 5;
            int c4  = i & 31;
            float4 v = *(const float4*)(W1 + (size_t)(w_off + k0 + kk) * D + c4 * 4);
            __half2 h01 = __floats2half2_rn(v.x, v.y);
            __half2 h23 = __floats2half2_rn(v.z, v.w);
            uint2 pv;
            pv.x = *(unsigned*)&h01; pv.y = *(unsigned*)&h23;
            *(uint2*)(&Bs[kk][c4 * 4]) = pv;
        }
        __syncthreads();

#pragma unroll
        for (int ks = 0; ks < KC / 16; ks++) {
            unsigned a[2][4];
            {
                int arow = (lane & 7) + ((lane >> 3) & 1) * 8;
                int acol = ks * 16 + (lane >> 4) * 8;
#pragma unroll
                for (int mi = 0; mi < 2; mi++)
                    ldm_x4(a[mi], smem_u32(&As[warp_m + mi * 16 + arow][acol]));
            }
            unsigned b[8][2];
            {
                int krow = ks * 16 + (lane & 7) + ((lane >> 3) & 1) * 8;
#pragma unroll
                for (int p = 0; p < 4; p++) {
                    unsigned r[4];
                    int ncol = warp_n + p * 16 + (lane >> 4) * 8;
                    ldm_x4_trans(r, smem_u32(&Bs[krow][ncol]));
                    b[2 * p][0]     = r[0]; b[2 * p][1]     = r[1];
                    b[2 * p + 1][0] = r[2]; b[2 * p + 1][1] = r[3];
                }
            }
#pragma unroll
            for (int mi = 0; mi < 2; mi++)
#pragma unroll
                for (int ni = 0; ni < 8; ni++)
                    mma_16816(acc[mi][ni], a[mi], b[ni]);
        }
    }

    if (is_rel) {
        if (tid < D) {
            int j = tid;
            float s = __ldg(b1 + j);
            const float* Wc = W1 + (size_t)256 * D + j;
#pragma unroll 8
            for (int k = 0; k < D; k++)
                s += rq_s[k] * __ldg(Wc + (size_t)k * D);
            cbias_s[j] = s;
        }
        __syncthreads();
    }

    const int erow = lane >> 2;
    const int ecol = (lane & 3) * 2;
#pragma unroll
    for (int mi = 0; mi < 2; mi++) {
#pragma unroll
        for (int ni = 0; ni < 8; ni++) {
            int col = warp_n + ni * 8 + ecol;
            float cb0 = cbias_s[col], cb1 = cbias_s[col + 1];
            int r0 = m0 + warp_m + mi * 16 + erow;
            if (r0 < M) {
                __half2 v = __floats2half2_rn(acc[mi][ni][0] + cb0,
                                              acc[mi][ni][1] + cb1);
                *(__half2*)(C + (size_t)r0 * D + col) = v;
            }
            int r1 = r0 + 8;
            if (r1 < M) {
                __half2 v = __floats2half2_rn(acc[mi][ni][2] + cb0,
                                              acc[mi][ni][3] + cb1);
                *(__half2*)(C + (size_t)r1 * D + col) = v;
            }
        }
    }
}

// ---------------------------------------------------------------------------
// Edge pass: 8 lanes per edge, lane l covers features [16l, 16l+16)
// (two uint4 per table). 2 edges (one int2 index pair) per group-iteration.
// ---------------------------------------------------------------------------
__device__ __forceinline__ float edge_partial(uint4 av, uint4 bv, uint4 cv,
                                              uint4 wv)
{
    const __half2 z2 = __float2half2_rn(0.f);
    __half2 acc;
    {
        __half2 x = __hmax2(__hadd2(__hadd2(*(__half2*)&av.x, *(__half2*)&bv.x),
                                    *(__half2*)&cv.x), z2);
        acc = __hmul2(x, *(__half2*)&wv.x);
    }
    {
        __half2 x = __hmax2(__hadd2(__hadd2(*(__half2*)&av.y, *(__half2*)&bv.y),
                                    *(__half2*)&cv.y), z2);
        acc = __hfma2(x, *(__half2*)&wv.y, acc);
    }
    {
        __half2 x = __hmax2(__hadd2(__hadd2(*(__half2*)&av.z, *(__half2*)&bv.z),
                                    *(__half2*)&cv.z), z2);
        acc = __hfma2(x, *(__half2*)&wv.z, acc);
    }
    {
        __half2 x = __hmax2(__hadd2(__hadd2(*(__half2*)&av.w, *(__half2*)&bv.w),
                                    *(__half2*)&cv.w), z2);
        acc = __hfma2(x, *(__half2*)&wv.w, acc);
    }
    float2 f = __half22float2(acc);
    return f.x + f.y;
}

__global__ __launch_bounds__(256) void edge_kernel(
    const int* __restrict__ edge_src,
    const int* __restrict__ edge_type,
    const int* __restrict__ edge_time,
    const float* __restrict__ b2,
    float* __restrict__ out, int E)
{
    const int l = threadIdx.x & 7;                          // lane in 8-group
    const int group  = (int)((blockIdx.x * 256u + threadIdx.x) >> 3);
    const int ngroup = (int)(gridDim.x * 256u / 8u);

    const uint4* __restrict__ np = (const uint4*)g_node_proj;
    const uint4* __restrict__ rp = (const uint4*)g_rel_proj;
    const uint4* __restrict__ tp = (const uint4*)g_time_proj;

    const uint4 wv0 = ((const uint4*)g_w2h)[l * 2];
    const uint4 wv1 = ((const uint4*)g_w2h)[l * 2 + 1];
    const float b2v = __ldg(b2);

    const int npair = E >> 1;
    for (int p = group; p < npair; p += ngroup) {
        int2 s = __ldg((const int2*)edge_src  + p);
        int2 r = __ldg((const int2*)edge_type + p);
        int2 t = __ldg((const int2*)edge_time + p);

        size_t oA = (size_t)l * 2;
        uint4 avA0 = np[(size_t)s.x * 16 + oA], avA1 = np[(size_t)s.x * 16 + oA + 1];
        uint4 bvA0 = rp[(size_t)r.x * 16 + oA], bvA1 = rp[(size_t)r.x * 16 + oA + 1];
        uint4 cvA0 = tp[(size_t)t.x * 16 + oA], cvA1 = tp[(size_t)t.x * 16 + oA + 1];
        uint4 avB0 = np[(size_t)s.y * 16 + oA], avB1 = np[(size_t)s.y * 16 + oA + 1];
        uint4 bvB0 = rp[(size_t)r.y * 16 + oA], bvB1 = rp[(size_t)r.y * 16 + oA + 1];
        uint4 cvB0 = tp[(size_t)t.y * 16 + oA], cvB1 = tp[(size_t)t.y * 16 + oA + 1];

        float dA = edge_partial(avA0, bvA0, cvA0, wv0)
                 + edge_partial(avA1, bvA1, cvA1, wv1);
        float dB = edge_partial(avB0, bvB0, cvB0, wv0)
                 + edge_partial(avB1, bvB1, cvB1, wv1);

#pragma unroll
        for (int off = 4; off; off >>= 1) {
            dA += __shfl_xor_sync(0xffffffffu, dA, off);
            dB += __shfl_xor_sync(0xffffffffu, dB, off);
        }

        if (l == 0) {
            out[p * 2]     = 1.f / (1.f + __expf(-(dA + b2v)));
            out[p * 2 + 1] = 1.f / (1.f + __expf(-(dB + b2v)));
        }
    }

    // Odd tail edge handled by group 0.
    if ((E & 1) && group == 0) {
        int e = E - 1;
        int s = __ldg(edge_src + e);
        int r = __ldg(edge_type + e);
        int t = __ldg(edge_time + e);
        size_t oA = (size_t)l * 2;
        float d = edge_partial(np[(size_t)s * 16 + oA], rp[(size_t)r * 16 + oA],
                               tp[(size_t)t * 16 + oA], wv0)
                + edge_partial(np[(size_t)s * 16 + oA + 1], rp[(size_t)r * 16 + oA + 1],
                               tp[(size_t)t * 16 + oA + 1], wv1);
#pragma unroll
        for (int off = 4; off; off >>= 1)
            d += __shfl_xor_sync(0xffffffffu, d, off);
        if (l == 0)
            out[e] = 1.f / (1.f + __expf(-(d + b2v)));
    }
}

// ---------------------------------------------------------------------------
extern "C" void kernel_launch(void* const* d_in, const int* in_sizes, int n_in,
                              void* d_out, int out_size)
{
    const float* h          = (const float*)d_in[0];
    const int*   edge_index = (const int*)d_in[1];
    const int*   edge_type  = (const int*)d_in[2];
    const int*   edge_time  = (const int*)d_in[3];
    const int*   query_rel  = (const int*)d_in[4];
    const float* rel_table  = (const float*)d_in[5];
    const float* time_table = (const float*)d_in[6];
    const float* W1         = (const float*)d_in[7];
    const float* b1         = (const float*)d_in[8];
    const float* W2         = (const float*)d_in[9];
    const float* b2         = (const float*)d_in[10];
    float*       out        = (float*)d_out;

    const int n_nodes = in_sizes[0] / D;
    const int n_rels  = in_sizes[5] / D;
    const int n_times = in_sizes[6] / D;
    const int E       = in_sizes[2];

    const int nb_node = (n_nodes + BM - 1) / BM;
    const int nb_rel  = (n_rels  + BM - 1) / BM;
    const int nb_time = (n_times + BM - 1) / BM;

    prep_kernel<<<nb_node + nb_rel + nb_time, 256>>>(
        h, rel_table, time_table, W1, b1, W2, query_rel,
        n_nodes, n_rels, n_times);

    // Persistent-ish edge grid: 2048 blocks x 32 groups x 2 edges per iter.
    edge_kernel<<<2048, 256>>>(edge_index, edge_type, edge_time, b2, out, E);
}